// round 5
// baseline (speedup 1.0000x reference)
#include <cuda_runtime.h>
#include <cuda_bf16.h>
#include <math.h>
#include <stdint.h>

// Problem constants
#define NB   2
#define C    256
#define H    64
#define W    64
#define HW   4096
#define M    8192
#define G    8
#define P    9
#define CG   32
#define OMC  216

// Scratch
__device__ float g_y[M * C];
__device__ float g_xproj[M * C];
__device__ float g_z[M * C];
__device__ float g_om[M * OMC];
__device__ float g_s[M * C];

__device__ __forceinline__ float silu(float t) { return t / (1.f + __expf(-t)); }

__device__ __forceinline__ uint32_t smem_u32_of(const void* p) {
    uint32_t a;
    asm("{ .reg .u64 t; cvta.to.shared.u64 t, %1; cvt.u32.u64 %0, t; }"
        : "=r"(a) : "l"(p));
    return a;
}

// bf16 hi/lo split
__device__ __forceinline__ void split1(float v, __nv_bfloat16& hi, __nv_bfloat16& lo) {
    hi = __float2bfloat16(v);
    lo = __float2bfloat16(v - __bfloat162float(hi));
}
__device__ __forceinline__ void split4(float4 f, uint2& uh, uint2& ul) {
    union { __nv_bfloat16 h[4]; uint2 u; } ph, pl;
    float v[4] = {f.x, f.y, f.z, f.w};
    #pragma unroll
    for (int i = 0; i < 4; i++) {
        __nv_bfloat16 hi = __float2bfloat16(v[i]);
        ph.h[i] = hi;
        pl.h[i] = __float2bfloat16(v[i] - __bfloat162float(hi));
    }
    uh = ph.u; ul = pl.u;
}

__device__ __forceinline__ void ldsm4(uint32_t* r, uint32_t addr) {
    asm volatile("ldmatrix.sync.aligned.m8n8.x4.shared.b16 {%0,%1,%2,%3}, [%4];"
                 : "=r"(r[0]), "=r"(r[1]), "=r"(r[2]), "=r"(r[3]) : "r"(addr));
}
__device__ __forceinline__ void mma16816(float* c, const uint32_t* a, uint32_t b0, uint32_t b1) {
    asm volatile(
        "mma.sync.aligned.m16n8k16.row.col.f32.bf16.bf16.f32 "
        "{%0,%1,%2,%3}, {%4,%5,%6,%7}, {%8,%9}, {%0,%1,%2,%3};"
        : "+f"(c[0]), "+f"(c[1]), "+f"(c[2]), "+f"(c[3])
        : "r"(a[0]), "r"(a[1]), "r"(a[2]), "r"(a[3]), "r"(b0), "r"(b1));
}

// SMEM layout: per stage, bf16 planes with 40-element (80B) padded rows.
// A_hi / A_lo: 128 rows x 40 ; B_hi / B_lo: 128 rows x 40
#define ROWB      80                    // bytes per padded row
#define PL_SZ     (128 * ROWB)          // 10240 bytes per plane
#define OFF_AHI   0
#define OFF_ALO   (PL_SZ)
#define OFF_BHI   (2 * PL_SZ)
#define OFF_BLO   (3 * PL_SZ)
#define STAGE_SZ  (4 * PL_SZ)           // 40960
#define SMEM_TOTAL (2 * STAGE_SZ)       // 81920 (also >= 128*132*4 transpose buf)

// ---------------------------------------------------------------------------
// mma.sync bf16x3-split GEMM, 128x128 CTA tile, K=256 in 8 chunks of 32.
// 8 warps: warp (wid>>2) in M (64 rows), (wid&3) in N (32 cols).
// MODE 0: conv1   A = x NCHW [c][p], B = w1[o][c];   epi BN1+SiLU -> NHWC
// MODE 1: inproj  A NHWC,            B = W[c][o];    epi +bias    -> NHWC
// MODE 2: offmask A NHWC,            B = [off|mask]; epi +bias    -> om (216)
// MODE 3: outproj A NHWC,            B = W[c][o];    epi bias+BN2+SiLU -> NCHW
// ---------------------------------------------------------------------------
template<int MODE>
__global__ __launch_bounds__(256, 1)
void gemm_w(const float* __restrict__ A,
            const float* __restrict__ B0,
            const float* __restrict__ B1,
            const float* __restrict__ bias0,
            const float* __restrict__ bias1,
            const float* __restrict__ bg, const float* __restrict__ bb,
            const float* __restrict__ bm, const float* __restrict__ bv,
            float* __restrict__ out)
{
    extern __shared__ char smem[];
    const uint32_t sb = smem_u32_of(smem);
    const int tid = threadIdx.x;
    const int lane = tid & 31, wid = tid >> 5;
    const int warpM = wid >> 2, warpN = wid & 3;     // 2 x 4
    const int bo = blockIdx.x * 128;
    const int bp = blockIdx.y * 128;
    const int n = bp >> 12;
    const int hwbase = bp & 4095;

    // staging regs for global loads
    float4 stA[4], stB[4];

    auto loadA = [&](int c0) {
        if (MODE == 0) {
            // x NCHW: tasks c(32) x p4(32), 4 per thread
            #pragma unroll
            for (int i = 0; i < 4; i++) {
                int id = tid + 256 * i;
                int c = id >> 5, p4 = id & 31;
                stA[i] = *(const float4*)&A[((size_t)n * C + c0 + c) * HW + hwbase + p4 * 4];
            }
        } else {
            // NHWC: row = tid>>1, khalf = (tid&1)*16
            const int row = tid >> 1, kh = (tid & 1) * 16;
            const float* ab = A + (size_t)(bp + row) * C + c0 + kh;
            #pragma unroll
            for (int q = 0; q < 4; q++) stA[q] = *(const float4*)&ab[q * 4];
        }
    };
    auto storeA = [&](int s) {
        char* hi = smem + s * STAGE_SZ + OFF_AHI;
        char* lo = smem + s * STAGE_SZ + OFF_ALO;
        if (MODE == 0) {
            #pragma unroll
            for (int i = 0; i < 4; i++) {
                int id = tid + 256 * i;
                int c = id >> 5, p4 = id & 31;
                float v[4] = {stA[i].x, stA[i].y, stA[i].z, stA[i].w};
                #pragma unroll
                for (int j = 0; j < 4; j++) {
                    __nv_bfloat16 h, l; split1(v[j], h, l);
                    int off = (p4 * 4 + j) * ROWB + c * 2;
                    *(__nv_bfloat16*)(hi + off) = h;
                    *(__nv_bfloat16*)(lo + off) = l;
                }
            }
        } else {
            const int row = tid >> 1, kh = (tid & 1) * 16;
            #pragma unroll
            for (int q = 0; q < 4; q++) {
                uint2 uh, ul; split4(stA[q], uh, ul);
                int off = row * ROWB + kh * 2 + q * 8;
                *(uint2*)(hi + off) = uh;
                *(uint2*)(lo + off) = ul;
            }
        }
    };
    auto loadB = [&](int c0) {
        if (MODE == 0) {
            // w1[o][c] k-contig: row = o
            const int row = tid >> 1, kh = (tid & 1) * 16;
            const float* wb = B0 + (size_t)(bo + row) * C + c0 + kh;
            #pragma unroll
            for (int q = 0; q < 4; q++) stB[q] = *(const float4*)&wb[q * 4];
        } else if (MODE == 2) {
            #pragma unroll
            for (int i = 0; i < 4; i++) {
                int id = tid + 256 * i;
                int k = id >> 5, n4 = id & 31;
                float v[4];
                #pragma unroll
                for (int j = 0; j < 4; j++) {
                    int col = bo + n4 * 4 + j;
                    float t = 0.f;
                    if (col < 144)      t = B0[(size_t)(c0 + k) * 144 + col];
                    else if (col < 216) t = B1[(size_t)(c0 + k) * 72 + col - 144];
                    v[j] = t;
                }
                stB[i] = make_float4(v[0], v[1], v[2], v[3]);
            }
        } else {
            // W[k][n] n-contig: tasks k(32) x n4(32)
            #pragma unroll
            for (int i = 0; i < 4; i++) {
                int id = tid + 256 * i;
                int k = id >> 5, n4 = id & 31;
                stB[i] = *(const float4*)&B0[(size_t)(c0 + k) * C + bo + n4 * 4];
            }
        }
    };
    auto storeB = [&](int s) {
        char* hi = smem + s * STAGE_SZ + OFF_BHI;
        char* lo = smem + s * STAGE_SZ + OFF_BLO;
        if (MODE == 0) {
            const int row = tid >> 1, kh = (tid & 1) * 16;
            #pragma unroll
            for (int q = 0; q < 4; q++) {
                uint2 uh, ul; split4(stB[q], uh, ul);
                int off = row * ROWB + kh * 2 + q * 8;
                *(uint2*)(hi + off) = uh;
                *(uint2*)(lo + off) = ul;
            }
        } else {
            #pragma unroll
            for (int i = 0; i < 4; i++) {
                int id = tid + 256 * i;
                int k = id >> 5, n4 = id & 31;
                float v[4] = {stB[i].x, stB[i].y, stB[i].z, stB[i].w};
                #pragma unroll
                for (int j = 0; j < 4; j++) {
                    __nv_bfloat16 h, l; split1(v[j], h, l);
                    int off = (n4 * 4 + j) * ROWB + k * 2;
                    *(__nv_bfloat16*)(hi + off) = h;
                    *(__nv_bfloat16*)(lo + off) = l;
                }
            }
        }
    };

    float acc[4][4][4];
    #pragma unroll
    for (int mt = 0; mt < 4; mt++)
        #pragma unroll
        for (int nt = 0; nt < 4; nt++)
            #pragma unroll
            for (int q = 0; q < 4; q++) acc[mt][nt][q] = 0.f;

    // ldmatrix per-lane addressing
    const int lrow = lane & 15;
    const int lkb  = (lane >> 4) * 16;     // 16B k-half select
    const uint32_t a_base = sb + (warpM * 64 + lrow) * ROWB + lkb;
    const uint32_t b_base = sb + (warpN * 32 + lrow) * ROWB + lkb;

    loadA(0); loadB(0);
    storeA(0); storeB(0);
    __syncthreads();

    #pragma unroll 1
    for (int chk = 0; chk < 8; chk++) {
        const int s = chk & 1;
        if (chk < 7) { loadA((chk + 1) * 32); loadB((chk + 1) * 32); }

        const uint32_t stg = s * STAGE_SZ;
        #pragma unroll
        for (int ks = 0; ks < 2; ks++) {
            const uint32_t kb = ks * 32;   // 16 bf16 = 32 bytes
            uint32_t aH[4][4], aL[4][4];
            #pragma unroll
            for (int mt = 0; mt < 4; mt++) {
                ldsm4(aH[mt], a_base + stg + OFF_AHI + mt * 16 * ROWB + kb);
                ldsm4(aL[mt], a_base + stg + OFF_ALO + mt * 16 * ROWB + kb);
            }
            uint32_t bH[2][4], bL[2][4];
            #pragma unroll
            for (int ng = 0; ng < 2; ng++) {
                ldsm4(bH[ng], b_base + stg + OFF_BHI + ng * 16 * ROWB + kb);
                ldsm4(bL[ng], b_base + stg + OFF_BLO + ng * 16 * ROWB + kb);
            }
            #pragma unroll
            for (int mt = 0; mt < 4; mt++)
                #pragma unroll
                for (int nt = 0; nt < 4; nt++) {
                    const int ng = nt >> 1, h = nt & 1;
                    mma16816(acc[mt][nt], aH[mt], bH[ng][h], bH[ng][2 + h]);
                    mma16816(acc[mt][nt], aH[mt], bL[ng][h], bL[ng][2 + h]);
                    mma16816(acc[mt][nt], aL[mt], bH[ng][h], bH[ng][2 + h]);
                }
        }
        if (chk < 7) { storeA(1 - s); storeB(1 - s); __syncthreads(); }
    }

    // -------- epilogue --------
    const int rql = lane >> 2;            // row-in-8
    const int cql = (lane & 3) * 2;       // col pair base

    if (MODE == 0 || MODE == 1) {
        float sc[8], bi[8];
        #pragma unroll
        for (int nt = 0; nt < 4; nt++)
            #pragma unroll
            for (int j = 0; j < 2; j++) {
                int o = bo + warpN * 32 + nt * 8 + cql + j;
                if (MODE == 0) {
                    float s0 = bg[o] * rsqrtf(bv[o] + 1e-3f);
                    sc[nt * 2 + j] = s0;
                    bi[nt * 2 + j] = bb[o] - bm[o] * s0;
                } else { sc[nt * 2 + j] = 1.f; bi[nt * 2 + j] = bias0[o]; }
            }
        #pragma unroll
        for (int mt = 0; mt < 4; mt++) {
            int p0 = bp + warpM * 64 + mt * 16 + rql;
            #pragma unroll
            for (int nt = 0; nt < 4; nt++) {
                int o = bo + warpN * 32 + nt * 8 + cql;
                float e0 = acc[mt][nt][0] * sc[nt*2] + bi[nt*2];
                float e1 = acc[mt][nt][1] * sc[nt*2+1] + bi[nt*2+1];
                float e2 = acc[mt][nt][2] * sc[nt*2] + bi[nt*2];
                float e3 = acc[mt][nt][3] * sc[nt*2+1] + bi[nt*2+1];
                if (MODE == 0) { e0 = silu(e0); e1 = silu(e1); e2 = silu(e2); e3 = silu(e3); }
                *(float2*)&out[(size_t)p0 * C + o]       = make_float2(e0, e1);
                *(float2*)&out[(size_t)(p0 + 8) * C + o] = make_float2(e2, e3);
            }
        }
    } else if (MODE == 2) {
        #pragma unroll
        for (int mt = 0; mt < 4; mt++) {
            int p0 = bp + warpM * 64 + mt * 16 + rql;
            #pragma unroll
            for (int nt = 0; nt < 4; nt++) {
                int o = bo + warpN * 32 + nt * 8 + cql;
                #pragma unroll
                for (int j = 0; j < 2; j++) {
                    int col = o + j;
                    if (col < OMC) {
                        float bi = (col < 144) ? bias0[col] : bias1[col - 144];
                        out[(size_t)p0 * OMC + col]       = acc[mt][nt][j] + bi;
                        out[(size_t)(p0 + 8) * OMC + col] = acc[mt][nt][2 + j] + bi;
                    }
                }
            }
        }
    } else {
        // MODE 3: transpose through smem -> coalesced NCHW float4 writes
        __syncthreads();
        float* ts = (float*)smem;          // [128 o][132 p]
        #pragma unroll
        for (int mt = 0; mt < 4; mt++) {
            int r0 = warpM * 64 + mt * 16 + rql;
            #pragma unroll
            for (int nt = 0; nt < 4; nt++) {
                int c0 = warpN * 32 + nt * 8 + cql;
                ts[(size_t)c0 * 132 + r0]           = acc[mt][nt][0];
                ts[(size_t)(c0 + 1) * 132 + r0]     = acc[mt][nt][1];
                ts[(size_t)c0 * 132 + r0 + 8]       = acc[mt][nt][2];
                ts[(size_t)(c0 + 1) * 132 + r0 + 8] = acc[mt][nt][3];
            }
        }
        __syncthreads();
        const int ol = tid >> 1;
        const int ph = (tid & 1) * 64;
        const int o = bo + ol;
        float sc = bg[o] * rsqrtf(bv[o] + 1e-5f);
        float bi = bb[o] - bm[o] * sc + bias0[o] * sc;
        float* op = &out[((size_t)(n * C + o)) * HW + hwbase + ph];
        #pragma unroll
        for (int q = 0; q < 16; q++) {
            float v0 = silu(ts[(size_t)ol * 132 + ph + q * 4 + 0] * sc + bi);
            float v1 = silu(ts[(size_t)ol * 132 + ph + q * 4 + 1] * sc + bi);
            float v2 = silu(ts[(size_t)ol * 132 + ph + q * 4 + 2] * sc + bi);
            float v3 = silu(ts[(size_t)ol * 132 + ph + q * 4 + 3] * sc + bi);
            *(float4*)&op[q * 4] = make_float4(v0, v1, v2, v3);
        }
    }
}

// ---------------------------------------------------------------------------
// depthwise 3x3 + LN + GELU (one block per pixel)
// ---------------------------------------------------------------------------
__global__ __launch_bounds__(256) void dwln_kernel(
    const float* __restrict__ y, const float* __restrict__ dww,
    const float* __restrict__ dwb, const float* __restrict__ lng,
    const float* __restrict__ lnb, float* __restrict__ z)
{
    const int p = blockIdx.x;
    const int c = threadIdx.x;
    const int n = p >> 12, hw = p & 4095;
    const int h = hw >> 6, w = hw & 63;

    float acc = dwb[c];
    #pragma unroll
    for (int ky = 0; ky < 3; ky++) {
        int hh = h + ky - 1;
        if (hh < 0 || hh > 63) continue;
        #pragma unroll
        for (int kx = 0; kx < 3; kx++) {
            int ww = w + kx - 1;
            if (ww < 0 || ww > 63) continue;
            acc += y[((size_t)(n << 12) + (hh << 6) + ww) * C + c] * dww[c * 9 + ky * 3 + kx];
        }
    }
    float s1 = acc, s2 = acc * acc;
    #pragma unroll
    for (int o = 16; o; o >>= 1) {
        s1 += __shfl_xor_sync(0xffffffffu, s1, o);
        s2 += __shfl_xor_sync(0xffffffffu, s2, o);
    }
    __shared__ float w1[8], w2[8];
    int warp = c >> 5, lane = c & 31;
    if (lane == 0) { w1[warp] = s1; w2[warp] = s2; }
    __syncthreads();
    if (warp == 0) {
        float a = lane < 8 ? w1[lane] : 0.f;
        float b = lane < 8 ? w2[lane] : 0.f;
        #pragma unroll
        for (int o = 4; o; o >>= 1) {
            a += __shfl_xor_sync(0xffffffffu, a, o);
            b += __shfl_xor_sync(0xffffffffu, b, o);
        }
        if (lane == 0) { w1[0] = a; w2[0] = b; }
    }
    __syncthreads();
    float mu = w1[0] * (1.f / 256.f);
    float var = w2[0] * (1.f / 256.f) - mu * mu;
    float zn = (acc - mu) * rsqrtf(var + 1e-5f) * lng[c] + lnb[c];
    float gl = 0.5f * zn * (1.f + erff(zn * 0.70710678118654752f));
    z[(size_t)p * C + c] = gl;
}

// ---------------------------------------------------------------------------
// deformable sampling (block = pixel, warp = group)
// ---------------------------------------------------------------------------
__device__ __forceinline__ float samp(const float* __restrict__ xb, int yy, int xx)
{
    if (yy >= 1 && yy <= 64 && xx >= 1 && xx <= 64)
        return xb[((size_t)((yy - 1) << 6) + (xx - 1)) * C];
    return 0.f;
}

__global__ __launch_bounds__(256) void dcn_kernel(
    const float* __restrict__ xproj, const float* __restrict__ om,
    float* __restrict__ s)
{
    const int p = blockIdx.x;
    const int t = threadIdx.x;
    const int g = t >> 5, lane = t & 31;
    const int n = p >> 12, hw = p & 4095;
    const int h = hw >> 6, w = hw & 63;

    const float* offp = om + (size_t)p * OMC + g * 18;
    const float* mlp  = om + (size_t)p * OMC + 144 + g * 9;

    float ml[9];
    float mx = -1e30f;
    #pragma unroll
    for (int i = 0; i < 9; i++) { ml[i] = mlp[i]; mx = fmaxf(mx, ml[i]); }
    float se = 0.f;
    #pragma unroll
    for (int i = 0; i < 9; i++) { ml[i] = expf(ml[i] - mx); se += ml[i]; }
    float inv = 1.f / se;

    const int ch = g * 32 + lane;
    const float* xb = xproj + (size_t)n * HW * C + ch;
    float acc = 0.f;
    #pragma unroll
    for (int i = 0; i < 9; i++) {
        float px = (float)w + (float)(i / 3) + offp[2 * i];
        float py = (float)h + (float)(i % 3) + offp[2 * i + 1];
        float x0f = floorf(px), y0f = floorf(py);
        float wx = px - x0f, wy = py - y0f;
        int x0 = (int)x0f, y0 = (int)y0f;
        float v00 = samp(xb, y0,     x0);
        float v10 = samp(xb, y0,     x0 + 1);
        float v01 = samp(xb, y0 + 1, x0);
        float v11 = samp(xb, y0 + 1, x0 + 1);
        float bil = v00 * (1.f - wx) * (1.f - wy) + v10 * wx * (1.f - wy)
                  + v01 * (1.f - wx) * wy         + v11 * wx * wy;
        acc += ml[i] * inv * bil;
    }
    s[(size_t)p * C + ch] = acc;
}

// ---------------------------------------------------------------------------
extern "C" void kernel_launch(void* const* d_in, const int* in_sizes, int n_in,
                              void* d_out, int out_size)
{
    const float* x        = (const float*)d_in[0];
    const float* conv1_w  = (const float*)d_in[1];
    const float* bn1_g    = (const float*)d_in[2];
    const float* bn1_b    = (const float*)d_in[3];
    const float* bn1_m    = (const float*)d_in[4];
    const float* bn1_v    = (const float*)d_in[5];
    const float* inproj_w = (const float*)d_in[6];
    const float* inproj_b = (const float*)d_in[7];
    const float* dw_w     = (const float*)d_in[8];
    const float* dw_b     = (const float*)d_in[9];
    const float* ln_g     = (const float*)d_in[10];
    const float* ln_b     = (const float*)d_in[11];
    const float* off_w    = (const float*)d_in[12];
    const float* off_b    = (const float*)d_in[13];
    const float* mask_w   = (const float*)d_in[14];
    const float* mask_b   = (const float*)d_in[15];
    const float* outproj_w= (const float*)d_in[16];
    const float* outproj_b= (const float*)d_in[17];
    const float* bn2_g    = (const float*)d_in[18];
    const float* bn2_b    = (const float*)d_in[19];
    const float* bn2_m    = (const float*)d_in[20];
    const float* bn2_v    = (const float*)d_in[21];
    float* out = (float*)d_out;

    float *y, *xproj, *z, *om, *s;
    cudaGetSymbolAddress((void**)&y,     g_y);
    cudaGetSymbolAddress((void**)&xproj, g_xproj);
    cudaGetSymbolAddress((void**)&z,     g_z);
    cudaGetSymbolAddress((void**)&om,    g_om);
    cudaGetSymbolAddress((void**)&s,     g_s);

    cudaFuncSetAttribute(gemm_w<0>, cudaFuncAttributeMaxDynamicSharedMemorySize, SMEM_TOTAL);
    cudaFuncSetAttribute(gemm_w<1>, cudaFuncAttributeMaxDynamicSharedMemorySize, SMEM_TOTAL);
    cudaFuncSetAttribute(gemm_w<2>, cudaFuncAttributeMaxDynamicSharedMemorySize, SMEM_TOTAL);
    cudaFuncSetAttribute(gemm_w<3>, cudaFuncAttributeMaxDynamicSharedMemorySize, SMEM_TOTAL);

    dim3 grd(2, 64);

    gemm_w<0><<<grd, 256, SMEM_TOTAL>>>(x, conv1_w, nullptr, nullptr, nullptr,
                                        bn1_g, bn1_b, bn1_m, bn1_v, y);
    gemm_w<1><<<grd, 256, SMEM_TOTAL>>>(y, inproj_w, nullptr, inproj_b, nullptr,
                                        nullptr, nullptr, nullptr, nullptr, xproj);
    dwln_kernel<<<M, 256>>>(y, dw_w, dw_b, ln_g, ln_b, z);
    gemm_w<2><<<grd, 256, SMEM_TOTAL>>>(z, off_w, mask_w, off_b, mask_b,
                                        nullptr, nullptr, nullptr, nullptr, om);
    dcn_kernel<<<M, 256>>>(xproj, om, s);
    gemm_w<3><<<grd, 256, SMEM_TOTAL>>>(s, outproj_w, nullptr, outproj_b, nullptr,
                                        bn2_g, bn2_b, bn2_m, bn2_v, out);
}

// round 7
// speedup vs baseline: 1.4082x; 1.4082x over previous
#include <cuda_runtime.h>
#include <cuda_bf16.h>
#include <math.h>
#include <stdint.h>

#define NB   2
#define C    256
#define H    64
#define W    64
#define HW   4096
#define M    8192
#define G    8
#define P    9
#define CG   32
#define OMC  216

typedef __nv_bfloat16 bf16;

// ---- scratch (device globals) ----
__device__ __align__(16) bf16 g_xh[M * C];
__device__ __align__(16) bf16 g_xl[M * C];
__device__ __align__(16) bf16 g_yh[M * C];
__device__ __align__(16) bf16 g_yl[M * C];
__device__ __align__(16) bf16 g_zh[M * C];
__device__ __align__(16) bf16 g_zl[M * C];
__device__ __align__(16) bf16 g_sh[M * C];
__device__ __align__(16) bf16 g_sl[M * C];
__device__ __align__(16) float g_xproj[M * C];
__device__ __align__(16) float g_om[M * OMC];
// weight planes, all [n-row][k] k-contig, 256x256
__device__ __align__(16) bf16 g_wch[C * C], g_wcl[C * C];   // conv1
__device__ __align__(16) bf16 g_wih[C * C], g_wil[C * C];   // inproj
__device__ __align__(16) bf16 g_woh[C * C], g_wol[C * C];   // outproj
__device__ __align__(16) bf16 g_wmh[C * C], g_wml[C * C];   // off|mask (216 real rows)

__device__ __forceinline__ float silu(float t) { return t / (1.f + __expf(-t)); }

__device__ __forceinline__ uint32_t smem_u32_of(const void* p) {
    uint32_t a;
    asm("{ .reg .u64 t; cvta.to.shared.u64 t, %1; cvt.u32.u64 %0, t; }"
        : "=r"(a) : "l"(p));
    return a;
}
__device__ __forceinline__ void split1(float v, bf16& hi, bf16& lo) {
    hi = __float2bfloat16(v);
    lo = __float2bfloat16(v - __bfloat162float(hi));
}
__device__ __forceinline__ void ldsm4(uint32_t* r, uint32_t addr) {
    asm volatile("ldmatrix.sync.aligned.m8n8.x4.shared.b16 {%0,%1,%2,%3}, [%4];"
                 : "=r"(r[0]), "=r"(r[1]), "=r"(r[2]), "=r"(r[3]) : "r"(addr));
}
__device__ __forceinline__ void mma16816(float* c, const uint32_t* a, uint32_t b0, uint32_t b1) {
    asm volatile(
        "mma.sync.aligned.m16n8k16.row.col.f32.bf16.bf16.f32 "
        "{%0,%1,%2,%3}, {%4,%5,%6,%7}, {%8,%9}, {%0,%1,%2,%3};"
        : "+f"(c[0]), "+f"(c[1]), "+f"(c[2]), "+f"(c[3])
        : "r"(a[0]), "r"(a[1]), "r"(a[2]), "r"(a[3]), "r"(b0), "r"(b1));
}
__device__ __forceinline__ void cp16(uint32_t dst, const void* src) {
    asm volatile("cp.async.cg.shared.global [%0], [%1], 16;" :: "r"(dst), "l"(src));
}
__device__ __forceinline__ void cp_commit() {
    asm volatile("cp.async.commit_group;");
}
template<int N> __device__ __forceinline__ void cp_wait() {
    asm volatile("cp.async.wait_group %0;" :: "n"(N));
}

// SMEM: per stage bf16 planes, 80B padded rows (conflict-free ldmatrix).
// A: 64 rows (hi/lo), B: 128 rows (hi/lo)
#define ROWB      80
#define OFF_AHI   0
#define OFF_ALO   (64 * ROWB)
#define OFF_BHI   (128 * ROWB)
#define OFF_BLO   (256 * ROWB)
#define STAGE_SZ  (384 * ROWB)          // 30720
#define SMEM_TOTAL (2 * STAGE_SZ)       // 61440

// ---------------------------------------------------------------------------
// prep kernels
// ---------------------------------------------------------------------------
union pk8 { bf16 h[8]; uint4 u; };

// x NCHW fp32 -> NHWC bf16 hi/lo planes
__global__ __launch_bounds__(256) void prep_x(const float* __restrict__ x,
                                              bf16* __restrict__ hi, bf16* __restrict__ lo)
{
    __shared__ float t[64][65];          // [c][hw]
    const int hw0 = blockIdx.x * 64, c0 = blockIdx.y * 64, n = blockIdx.z;
    const int tid = threadIdx.x;
    #pragma unroll
    for (int r = 0; r < 4; r++) {
        int c = (tid >> 4) + r * 16;
        float4 v = *(const float4*)&x[((size_t)n * C + c0 + c) * HW + hw0 + (tid & 15) * 4];
        t[c][(tid & 15) * 4 + 0] = v.x;
        t[c][(tid & 15) * 4 + 1] = v.y;
        t[c][(tid & 15) * 4 + 2] = v.z;
        t[c][(tid & 15) * 4 + 3] = v.w;
    }
    __syncthreads();
    const int hwl = tid >> 2, cq = (tid & 3) * 16;
    pk8 hb[2], lb[2];
    #pragma unroll
    for (int j = 0; j < 16; j++)
        split1(t[cq + j][hwl], hb[j >> 3].h[j & 7], lb[j >> 3].h[j & 7]);
    size_t base = ((size_t)n * HW + hw0 + hwl) * C + c0 + cq;
    *(uint4*)&hi[base] = hb[0].u; *(uint4*)&hi[base + 8] = hb[1].u;
    *(uint4*)&lo[base] = lb[0].u; *(uint4*)&lo[base + 8] = lb[1].u;
}

// row-major weight [n][k] -> planes (conv1_w)
__global__ __launch_bounds__(256) void prep_wrow(const float* __restrict__ wsrc,
                                                 bf16* __restrict__ hi, bf16* __restrict__ lo)
{
    const int row = blockIdx.x, tid = threadIdx.x;
    bf16 hh, ll; split1(wsrc[(size_t)row * C + tid], hh, ll);
    hi[(size_t)row * C + tid] = hh;
    lo[(size_t)row * C + tid] = ll;
}

// Wk[k][n] fp32 -> out[n][k] planes (inproj/outproj)
__global__ __launch_bounds__(256) void prep_wt(const float* __restrict__ Wk,
                                               bf16* __restrict__ hi, bf16* __restrict__ lo)
{
    __shared__ float t[64][65];          // [n][k]
    const int k0 = blockIdx.x * 64, n0 = blockIdx.y * 64;
    const int tid = threadIdx.x;
    #pragma unroll
    for (int r = 0; r < 4; r++) {
        int k = k0 + (tid >> 4) + r * 16;
        float4 v = *(const float4*)&Wk[(size_t)k * C + n0 + (tid & 15) * 4];
        t[(tid & 15) * 4 + 0][k - k0] = v.x;
        t[(tid & 15) * 4 + 1][k - k0] = v.y;
        t[(tid & 15) * 4 + 2][k - k0] = v.z;
        t[(tid & 15) * 4 + 3][k - k0] = v.w;
    }
    __syncthreads();
    const int nl = tid >> 2, kq = (tid & 3) * 16;
    pk8 hb[2], lb[2];
    #pragma unroll
    for (int j = 0; j < 16; j++)
        split1(t[nl][kq + j], hb[j >> 3].h[j & 7], lb[j >> 3].h[j & 7]);
    size_t base = (size_t)(n0 + nl) * C + k0 + kq;
    *(uint4*)&hi[base] = hb[0].u; *(uint4*)&hi[base + 8] = hb[1].u;
    *(uint4*)&lo[base] = lb[0].u; *(uint4*)&lo[base + 8] = lb[1].u;
}

// combined [off|mask] -> out[n(256 pad)][k] planes
__global__ __launch_bounds__(256) void prep_off(const float* __restrict__ offw,
                                                const float* __restrict__ maskw,
                                                bf16* __restrict__ hi, bf16* __restrict__ lo)
{
    const int nrow = blockIdx.x, k = threadIdx.x;
    float v = 0.f;
    if (nrow < 144)      v = offw[(size_t)k * 144 + nrow];
    else if (nrow < 216) v = maskw[(size_t)k * 72 + nrow - 144];
    bf16 hh, ll; split1(v, hh, ll);
    hi[(size_t)nrow * C + k] = hh;
    lo[(size_t)nrow * C + k] = ll;
}

// ---------------------------------------------------------------------------
// Pipelined split-bf16 HMMA GEMM: 64(M) x 128(N) x 32(BK), 8 chunks.
// A planes NHWC [p][k], B planes [n][k]. 8 warps = 2(M) x 4(N).
// MODE 0: epi BN1+SiLU -> y planes.   MODE 1: +bias -> xproj fp32.
// MODE 2: +bias (216 guard) -> om.    MODE 3: bias+BN2+SiLU -> out NCHW fp32.
// ---------------------------------------------------------------------------
template<int MODE>
__global__ __launch_bounds__(256, 2)
void gemm_p(const bf16* __restrict__ Ah, const bf16* __restrict__ Al,
            const bf16* __restrict__ Bh, const bf16* __restrict__ Bl,
            const float* __restrict__ bias0, const float* __restrict__ bias1,
            const float* __restrict__ bg, const float* __restrict__ bb,
            const float* __restrict__ bm, const float* __restrict__ bv,
            float* __restrict__ outF, bf16* __restrict__ outHi, bf16* __restrict__ outLo)
{
    extern __shared__ char smem[];
    const uint32_t sb = smem_u32_of(smem);
    const int tid = threadIdx.x;
    const int lane = tid & 31, wid = tid >> 5;
    const int warpM = wid >> 2, warpN = wid & 3;
    const int bo = blockIdx.x * 128;
    const int bp = blockIdx.y * 64;

    auto issue = [&](int s, int chk) {
        const int c0b = chk * 64;   // byte offset within a 512B row
        const uint32_t stg = sb + s * STAGE_SZ;
        #pragma unroll
        for (int i = 0; i < 6; i++) {
            int id = tid + 256 * i;
            if (id < 512) {
                int pl = id >> 8, rem = id & 255, row = rem >> 2, q = rem & 3;
                const char* src = (const char*)(pl ? Al : Ah)
                                  + ((size_t)(bp + row) * C) * 2 + c0b + q * 16;
                cp16(stg + (pl ? OFF_ALO : OFF_AHI) + row * ROWB + q * 16, src);
            } else {
                int id2 = id - 512;
                int pl = id2 >> 9, rem = id2 & 511, row = rem >> 2, q = rem & 3;
                const char* src = (const char*)(pl ? Bl : Bh)
                                  + ((size_t)(bo + row) * C) * 2 + c0b + q * 16;
                cp16(stg + (pl ? OFF_BLO : OFF_BHI) + row * ROWB + q * 16, src);
            }
        }
        cp_commit();
    };

    float acc[2][4][4];
    #pragma unroll
    for (int mt = 0; mt < 2; mt++)
        #pragma unroll
        for (int nt = 0; nt < 4; nt++)
            #pragma unroll
            for (int q = 0; q < 4; q++) acc[mt][nt][q] = 0.f;

    const int lrow = lane & 15;
    const int lhalf = (lane >> 4) * 16;

    issue(0, 0);
    #pragma unroll 1
    for (int chk = 0; chk < 8; chk++) {
        if (chk < 7) { issue((chk + 1) & 1, chk + 1); cp_wait<1>(); }
        else         { cp_wait<0>(); }
        __syncthreads();
        const uint32_t stg = sb + (chk & 1) * STAGE_SZ;
        #pragma unroll
        for (int ks = 0; ks < 2; ks++) {
            const uint32_t kb = ks * 32 + lhalf;
            uint32_t aH[2][4], aL[2][4], bH[2][4], bL[2][4];
            #pragma unroll
            for (int mt = 0; mt < 2; mt++) {
                uint32_t r = (warpM * 32 + mt * 16 + lrow) * ROWB + kb;
                ldsm4(aH[mt], stg + OFF_AHI + r);
                ldsm4(aL[mt], stg + OFF_ALO + r);
            }
            #pragma unroll
            for (int ng = 0; ng < 2; ng++) {
                uint32_t r = (warpN * 32 + ng * 16 + lrow) * ROWB + kb;
                ldsm4(bH[ng], stg + OFF_BHI + r);
                ldsm4(bL[ng], stg + OFF_BLO + r);
            }
            #pragma unroll
            for (int mt = 0; mt < 2; mt++)
                #pragma unroll
                for (int nt = 0; nt < 4; nt++) {
                    const int ng = nt >> 1, hsel = nt & 1;
                    mma16816(acc[mt][nt], aH[mt], bH[ng][hsel], bH[ng][2 + hsel]);
                    mma16816(acc[mt][nt], aH[mt], bL[ng][hsel], bL[ng][2 + hsel]);
                    mma16816(acc[mt][nt], aL[mt], bH[ng][hsel], bH[ng][2 + hsel]);
                }
        }
        __syncthreads();
    }

    // -------- epilogue --------
    const int rql = lane >> 2;
    const int cql = (lane & 3) * 2;

    if (MODE == 0) {
        #pragma unroll
        for (int mt = 0; mt < 2; mt++) {
            int p0 = bp + warpM * 32 + mt * 16 + rql;
            #pragma unroll
            for (int nt = 0; nt < 4; nt++) {
                int o = bo + warpN * 32 + nt * 8 + cql;
                float s0 = bg[o] * rsqrtf(bv[o] + 1e-3f);
                float s1 = bg[o+1] * rsqrtf(bv[o+1] + 1e-3f);
                float b0 = bb[o] - bm[o] * s0;
                float b1 = bb[o+1] - bm[o+1] * s1;
                float e0 = silu(acc[mt][nt][0] * s0 + b0);
                float e1 = silu(acc[mt][nt][1] * s1 + b1);
                float e2 = silu(acc[mt][nt][2] * s0 + b0);
                float e3 = silu(acc[mt][nt][3] * s1 + b1);
                __nv_bfloat162 h01, l01, h23, l23;
                split1(e0, h01.x, l01.x); split1(e1, h01.y, l01.y);
                split1(e2, h23.x, l23.x); split1(e3, h23.y, l23.y);
                *(__nv_bfloat162*)&outHi[(size_t)p0 * C + o] = h01;
                *(__nv_bfloat162*)&outLo[(size_t)p0 * C + o] = l01;
                *(__nv_bfloat162*)&outHi[(size_t)(p0 + 8) * C + o] = h23;
                *(__nv_bfloat162*)&outLo[(size_t)(p0 + 8) * C + o] = l23;
            }
        }
    } else if (MODE == 1) {
        #pragma unroll
        for (int mt = 0; mt < 2; mt++) {
            int p0 = bp + warpM * 32 + mt * 16 + rql;
            #pragma unroll
            for (int nt = 0; nt < 4; nt++) {
                int o = bo + warpN * 32 + nt * 8 + cql;
                float b0 = bias0[o], b1 = bias0[o + 1];
                *(float2*)&outF[(size_t)p0 * C + o] =
                    make_float2(acc[mt][nt][0] + b0, acc[mt][nt][1] + b1);
                *(float2*)&outF[(size_t)(p0 + 8) * C + o] =
                    make_float2(acc[mt][nt][2] + b0, acc[mt][nt][3] + b1);
            }
        }
    } else if (MODE == 2) {
        #pragma unroll
        for (int mt = 0; mt < 2; mt++) {
            int p0 = bp + warpM * 32 + mt * 16 + rql;
            #pragma unroll
            for (int nt = 0; nt < 4; nt++) {
                int o = bo + warpN * 32 + nt * 8 + cql;
                #pragma unroll
                for (int j = 0; j < 2; j++) {
                    int col = o + j;
                    if (col < OMC) {
                        float bi = (col < 144) ? bias0[col] : bias1[col - 144];
                        outF[(size_t)p0 * OMC + col]       = acc[mt][nt][j] + bi;
                        outF[(size_t)(p0 + 8) * OMC + col] = acc[mt][nt][2 + j] + bi;
                    }
                }
            }
        }
    } else {
        // transpose via smem -> coalesced NCHW float4
        float* ts = (float*)smem;          // [128 o][68 p]
        #pragma unroll
        for (int mt = 0; mt < 2; mt++) {
            int r0 = warpM * 32 + mt * 16 + rql;
            #pragma unroll
            for (int nt = 0; nt < 4; nt++) {
                int c0t = warpN * 32 + nt * 8 + cql;
                ts[(size_t)c0t * 68 + r0]           = acc[mt][nt][0];
                ts[(size_t)(c0t + 1) * 68 + r0]     = acc[mt][nt][1];
                ts[(size_t)c0t * 68 + r0 + 8]       = acc[mt][nt][2];
                ts[(size_t)(c0t + 1) * 68 + r0 + 8] = acc[mt][nt][3];
            }
        }
        __syncthreads();
        const int n = bp >> 12, hwbase = bp & 4095;
        const int ol = tid >> 1, ph = (tid & 1) * 32;
        const int o = bo + ol;
        float sc = bg[o] * rsqrtf(bv[o] + 1e-5f);
        float bi = bb[o] - bm[o] * sc + bias0[o] * sc;
        float* op = &outF[((size_t)(n * C + o)) * HW + hwbase + ph];
        #pragma unroll
        for (int q = 0; q < 8; q++) {
            float v0 = silu(ts[(size_t)ol * 68 + ph + q * 4 + 0] * sc + bi);
            float v1 = silu(ts[(size_t)ol * 68 + ph + q * 4 + 1] * sc + bi);
            float v2 = silu(ts[(size_t)ol * 68 + ph + q * 4 + 2] * sc + bi);
            float v3 = silu(ts[(size_t)ol * 68 + ph + q * 4 + 3] * sc + bi);
            *(float4*)&op[q * 4] = make_float4(v0, v1, v2, v3);
        }
    }
}

// ---------------------------------------------------------------------------
// depthwise 3x3 + LN + GELU; reads y planes, writes z planes
// ---------------------------------------------------------------------------
__global__ __launch_bounds__(256) void dwln_kernel(
    const bf16* __restrict__ yh, const bf16* __restrict__ yl,
    const float* __restrict__ dww, const float* __restrict__ dwb,
    const float* __restrict__ lng, const float* __restrict__ lnb,
    bf16* __restrict__ zh, bf16* __restrict__ zl)
{
    const int p = blockIdx.x;
    const int c = threadIdx.x;
    const int n = p >> 12, hw = p & 4095;
    const int h = hw >> 6, w = hw & 63;

    float acc = dwb[c];
    #pragma unroll
    for (int ky = 0; ky < 3; ky++) {
        int hh = h + ky - 1;
        if (hh < 0 || hh > 63) continue;
        #pragma unroll
        for (int kx = 0; kx < 3; kx++) {
            int ww = w + kx - 1;
            if (ww < 0 || ww > 63) continue;
            size_t idx = ((size_t)(n << 12) + (hh << 6) + ww) * C + c;
            float v = __bfloat162float(yh[idx]) + __bfloat162float(yl[idx]);
            acc += v * dww[c * 9 + ky * 3 + kx];
        }
    }
    float s1 = acc, s2 = acc * acc;
    #pragma unroll
    for (int o = 16; o; o >>= 1) {
        s1 += __shfl_xor_sync(0xffffffffu, s1, o);
        s2 += __shfl_xor_sync(0xffffffffu, s2, o);
    }
    __shared__ float w1[8], w2[8];
    int warp = c >> 5, lane = c & 31;
    if (lane == 0) { w1[warp] = s1; w2[warp] = s2; }
    __syncthreads();
    if (warp == 0) {
        float a = lane < 8 ? w1[lane] : 0.f;
        float b = lane < 8 ? w2[lane] : 0.f;
        #pragma unroll
        for (int o = 4; o; o >>= 1) {
            a += __shfl_xor_sync(0xffffffffu, a, o);
            b += __shfl_xor_sync(0xffffffffu, b, o);
        }
        if (lane == 0) { w1[0] = a; w2[0] = b; }
    }
    __syncthreads();
    float mu = w1[0] * (1.f / 256.f);
    float var = w2[0] * (1.f / 256.f) - mu * mu;
    float zn = (acc - mu) * rsqrtf(var + 1e-5f) * lng[c] + lnb[c];
    float gl = 0.5f * zn * (1.f + erff(zn * 0.70710678118654752f));
    bf16 hh2, ll2; split1(gl, hh2, ll2);
    zh[(size_t)p * C + c] = hh2;
    zl[(size_t)p * C + c] = ll2;
}

// ---------------------------------------------------------------------------
// deformable sampling; reads xproj fp32 + om, writes s planes
// ---------------------------------------------------------------------------
__device__ __forceinline__ float samp(const float* __restrict__ xb, int yy, int xx)
{
    if (yy >= 1 && yy <= 64 && xx >= 1 && xx <= 64)
        return xb[((size_t)((yy - 1) << 6) + (xx - 1)) * C];
    return 0.f;
}

__global__ __launch_bounds__(256) void dcn_kernel(
    const float* __restrict__ xproj, const float* __restrict__ om,
    bf16* __restrict__ sh, bf16* __restrict__ sl)
{
    const int p = blockIdx.x;
    const int t = threadIdx.x;
    const int g = t >> 5, lane = t & 31;
    const int n = p >> 12, hw = p & 4095;
    const int h = hw >> 6, w = hw & 63;

    const float* offp = om + (size_t)p * OMC + g * 18;
    const float* mlp  = om + (size_t)p * OMC + 144 + g * 9;

    float ml[9];
    float mx = -1e30f;
    #pragma unroll
    for (int i = 0; i < 9; i++) { ml[i] = mlp[i]; mx = fmaxf(mx, ml[i]); }
    float se = 0.f;
    #pragma unroll
    for (int i = 0; i < 9; i++) { ml[i] = expf(ml[i] - mx); se += ml[i]; }
    float inv = 1.f / se;

    const int ch = g * 32 + lane;
    const float* xb = xproj + (size_t)n * HW * C + ch;
    float acc = 0.f;
    #pragma unroll
    for (int i = 0; i < 9; i++) {
        float px = (float)w + (float)(i / 3) + offp[2 * i];
        float py = (float)h + (float)(i % 3) + offp[2 * i + 1];
        float x0f = floorf(px), y0f = floorf(py);
        float wx = px - x0f, wy = py - y0f;
        int x0 = (int)x0f, y0 = (int)y0f;
        float v00 = samp(xb, y0,     x0);
        float v10 = samp(xb, y0,     x0 + 1);
        float v01 = samp(xb, y0 + 1, x0);
        float v11 = samp(xb, y0 + 1, x0 + 1);
        float bil = v00 * (1.f - wx) * (1.f - wy) + v10 * wx * (1.f - wy)
                  + v01 * (1.f - wx) * wy         + v11 * wx * wy;
        acc += ml[i] * inv * bil;
    }
    bf16 hh2, ll2; split1(acc, hh2, ll2);
    sh[(size_t)p * C + ch] = hh2;
    sl[(size_t)p * C + ch] = ll2;
}

// ---------------------------------------------------------------------------
extern "C" void kernel_launch(void* const* d_in, const int* in_sizes, int n_in,
                              void* d_out, int out_size)
{
    const float* x        = (const float*)d_in[0];
    const float* conv1_w  = (const float*)d_in[1];
    const float* bn1_g    = (const float*)d_in[2];
    const float* bn1_b    = (const float*)d_in[3];
    const float* bn1_m    = (const float*)d_in[4];
    const float* bn1_v    = (const float*)d_in[5];
    const float* inproj_w = (const float*)d_in[6];
    const float* inproj_b = (const float*)d_in[7];
    const float* dw_w     = (const float*)d_in[8];
    const float* dw_b     = (const float*)d_in[9];
    const float* ln_g     = (const float*)d_in[10];
    const float* ln_b     = (const float*)d_in[11];
    const float* off_w    = (const float*)d_in[12];
    const float* off_b    = (const float*)d_in[13];
    const float* mask_w   = (const float*)d_in[14];
    const float* mask_b   = (const float*)d_in[15];
    const float* outproj_w= (const float*)d_in[16];
    const float* outproj_b= (const float*)d_in[17];
    const float* bn2_g    = (const float*)d_in[18];
    const float* bn2_b    = (const float*)d_in[19];
    const float* bn2_m    = (const float*)d_in[20];
    const float* bn2_v    = (const float*)d_in[21];
    float* out = (float*)d_out;

    bf16 *xh, *xl, *yh, *yl, *zh, *zl, *sh, *sl;
    bf16 *wch, *wcl, *wih, *wil, *woh, *wol, *wmh, *wml;
    float *xproj, *om;
    cudaGetSymbolAddress((void**)&xh, g_xh); cudaGetSymbolAddress((void**)&xl, g_xl);
    cudaGetSymbolAddress((void**)&yh, g_yh); cudaGetSymbolAddress((void**)&yl, g_yl);
    cudaGetSymbolAddress((void**)&zh, g_zh); cudaGetSymbolAddress((void**)&zl, g_zl);
    cudaGetSymbolAddress((void**)&sh, g_sh); cudaGetSymbolAddress((void**)&sl, g_sl);
    cudaGetSymbolAddress((void**)&wch, g_wch); cudaGetSymbolAddress((void**)&wcl, g_wcl);
    cudaGetSymbolAddress((void**)&wih, g_wih); cudaGetSymbolAddress((void**)&wil, g_wil);
    cudaGetSymbolAddress((void**)&woh, g_woh); cudaGetSymbolAddress((void**)&wol, g_wol);
    cudaGetSymbolAddress((void**)&wmh, g_wmh); cudaGetSymbolAddress((void**)&wml, g_wml);
    cudaGetSymbolAddress((void**)&xproj, g_xproj);
    cudaGetSymbolAddress((void**)&om, g_om);

    cudaFuncSetAttribute(gemm_p<0>, cudaFuncAttributeMaxDynamicSharedMemorySize, SMEM_TOTAL);
    cudaFuncSetAttribute(gemm_p<1>, cudaFuncAttributeMaxDynamicSharedMemorySize, SMEM_TOTAL);
    cudaFuncSetAttribute(gemm_p<2>, cudaFuncAttributeMaxDynamicSharedMemorySize, SMEM_TOTAL);
    cudaFuncSetAttribute(gemm_p<3>, cudaFuncAttributeMaxDynamicSharedMemorySize, SMEM_TOTAL);

    // ---- prep ----
    prep_x<<<dim3(64, 4, 2), 256>>>(x, xh, xl);
    prep_wrow<<<256, 256>>>(conv1_w, wch, wcl);
    prep_wt<<<dim3(4, 4), 256>>>(inproj_w, wih, wil);
    prep_wt<<<dim3(4, 4), 256>>>(outproj_w, woh, wol);
    prep_off<<<256, 256>>>(off_w, mask_w, wmh, wml);

    dim3 grd(2, 128);
    // ---- pipeline ----
    gemm_p<0><<<grd, 256, SMEM_TOTAL>>>(xh, xl, wch, wcl, nullptr, nullptr,
                                        bn1_g, bn1_b, bn1_m, bn1_v,
                                        nullptr, yh, yl);
    gemm_p<1><<<grd, 256, SMEM_TOTAL>>>(yh, yl, wih, wil, inproj_b, nullptr,
                                        nullptr, nullptr, nullptr, nullptr,
                                        xproj, nullptr, nullptr);
    dwln_kernel<<<M, 256>>>(yh, yl, dw_w, dw_b, ln_g, ln_b, zh, zl);
    gemm_p<2><<<grd, 256, SMEM_TOTAL>>>(zh, zl, wmh, wml, off_b, mask_b,
                                        nullptr, nullptr, nullptr, nullptr,
                                        om, nullptr, nullptr);
    dcn_kernel<<<M, 256>>>(xproj, om, sh, sl);
    gemm_p<3><<<grd, 256, SMEM_TOTAL>>>(sh, sl, woh, wol, outproj_b, nullptr,
                                        bn2_g, bn2_b, bn2_m, bn2_v,
                                        out, nullptr, nullptr);
}